// round 6
// baseline (speedup 1.0000x reference)
#include <cuda_runtime.h>
#include <cstdint>

#define L_LEVELS 12
#define T_SIZE   (1u << 19)
#define T_MASK   (T_SIZE - 1u)
#define N_POINTS 524288
#define D_OUT    257
#define FEAT     24          // L * F
#define BLOCK    64          // threads per block = points per block (2 warps)
#define EMB_PAD  28          // padded row stride in floats (16B aligned, 7 float4s)

// ---------- packed f32x2 helpers (Blackwell FFMA2 path) ----------
__device__ __forceinline__ unsigned long long pack2(float lo, float hi) {
    unsigned long long r;
    asm("mov.b64 %0, {%1, %2};" : "=l"(r) : "f"(lo), "f"(hi));
    return r;
}
__device__ __forceinline__ void unpack2(unsigned long long v, float& lo, float& hi) {
    asm("mov.b64 {%0, %1}, %2;" : "=f"(lo), "=f"(hi) : "l"(v));
}
__device__ __forceinline__ unsigned long long fma2(unsigned long long a,
                                                   unsigned long long b,
                                                   unsigned long long c) {
    unsigned long long d;
    asm("fma.rn.f32x2 %0, %1, %2, %3;" : "=l"(d) : "l"(a), "l"(b), "l"(c));
    return d;
}

// Per-level grid resolutions: floor(16 * growth^l), growth = exp(ln(128)/11).
__device__ __constant__ float RESF[L_LEVELS] = {
    16.f, 24.f, 38.f, 60.f, 93.f, 145.f, 225.f, 350.f, 545.f, 847.f, 1317.f, 2048.f
};

// Gather the (ox=0, ox=1) corner pair for one (oy,oz). When cx is even the two
// hashed entries are idx0 and idx0^1 -> one aligned LDG.128; otherwise two LDG.64.
// Branch-free via predicated PTX (avoids BSSY/BSYNC divergence overhead).
__device__ __forceinline__ void gather_pair(const float2* __restrict__ tl,
                                            unsigned cx, unsigned cx1, unsigned r,
                                            unsigned cx_odd,
                                            float2& fa, float2& fb)
{
    unsigned i0 = (cx  ^ r) & T_MASK;
    unsigned i1 = (cx1 ^ r) & T_MASK;   // when cx even: i1 == i0^1

    const float* p128 = (const float*)(tl + (i0 & ~1u));  // 16B aligned
    const float* pa   = (const float*)(tl + i0);
    const float* pb   = (const float*)(tl + i1);

    float t0, t1, t2, t3;
    asm("{\n\t"
        ".reg .pred p;\n\t"
        "setp.eq.u32 p, %4, 0;\n\t"
        "@p  ld.global.nc.v4.f32 {%0,%1,%2,%3}, [%5];\n\t"
        "@!p ld.global.nc.v2.f32 {%0,%1}, [%6];\n\t"
        "@!p ld.global.nc.v2.f32 {%2,%3}, [%7];\n\t"
        "}"
        : "=f"(t0), "=f"(t1), "=f"(t2), "=f"(t3)
        : "r"(cx_odd), "l"(p128), "l"(pa), "l"(pb));

    // Merged path loads {entry i0&~1, entry i0|1}. If i0 is odd, ox=0's entry is
    // the high half -> swap. (Odd-cx path: t0..t3 already in (fa,fb) order.)
    bool swap = (cx_odd == 0u) && (i0 & 1u);
    fa.x = swap ? t2 : t0;
    fa.y = swap ? t3 : t1;
    fb.x = swap ? t0 : t2;
    fb.y = swap ? t1 : t3;
}

__global__ __launch_bounds__(BLOCK, 8)
void hashgrid_fused_kernel(const float*  __restrict__ xin,    // [N,3]
                           const float2* __restrict__ tab,    // [12, T] of float2
                           const float*  __restrict__ W,      // [24, 257]
                           const float*  __restrict__ bias,   // [257]
                           float*        __restrict__ out)    // [N, 257]
{
    __shared__ float semb[BLOCK][EMB_PAD];  // 24 features/row, padded to 28
    __shared__ float wc256[FEAT];           // W[:,256]
    __shared__ float b256s;

    const int tid = threadIdx.x;

    if (tid < FEAT) wc256[tid] = W[tid * D_OUT + 256];
    if (tid == FEAT) b256s = bias[256];
    __syncthreads();

    // ---------------- Phase 1: hash encode (thread = point) ----------------
    const int p = blockIdx.x * BLOCK + tid;
    const float x = xin[3 * p + 0];
    const float y = xin[3 * p + 1];
    const float z = xin[3 * p + 2];

    const unsigned P1 = 2654435761u;
    const unsigned P2 = 805459861u;

    float acc256 = b256s;

#pragma unroll
    for (int l = 0; l < L_LEVELS; l++) {
        const float resf = RESF[l];
        const float2* tl = tab + (size_t)l * T_SIZE;

        float px = x * resf, py = y * resf, pz = z * resf;
        float fx = floorf(px), fy = floorf(py), fz = floorf(pz);
        float tx = px - fx,   ty = py - fy,   tz = pz - fz;

        unsigned cx = (unsigned)fx, cy = (unsigned)fy, cz = (unsigned)fz;
        unsigned cx1 = cx + 1u;
        unsigned cx_odd = cx & 1u;
        unsigned hy0 = cy * P1,   hy1 = hy0 + P1;
        unsigned hz0 = cz * P2,   hz1 = hz0 + P2;

        // 4 (oy,oz) pairs; each gathers corner pair (ox=0, ox=1)
        float2 fa0, fb0, fa1, fb1, fa2, fb2, fa3, fb3;
        gather_pair(tl, cx, cx1, hy0 ^ hz0, cx_odd, fa0, fb0);  // (oy=0, oz=0)
        gather_pair(tl, cx, cx1, hy0 ^ hz1, cx_odd, fa1, fb1);  // (oy=0, oz=1)
        gather_pair(tl, cx, cx1, hy1 ^ hz0, cx_odd, fa2, fb2);  // (oy=1, oz=0)
        gather_pair(tl, cx, cx1, hy1 ^ hz1, cx_odd, fa3, fb3);  // (oy=1, oz=1)

        const float ux = 1.0f - tx, uy = 1.0f - ty, uz = 1.0f - tz;
        // weights for (oy,oz) combos, split by ox
        float w00 = uy * uz, w01 = uy * tz, w10 = ty * uz, w11 = ty * tz;

        float e0 = 0.0f, e1 = 0.0f;
        // ox = 0 (weight factor ux)
        float s0 = 0.0f, s1 = 0.0f;
        s0 = fmaf(w00, fa0.x, s0);  s1 = fmaf(w00, fa0.y, s1);
        s0 = fmaf(w01, fa1.x, s0);  s1 = fmaf(w01, fa1.y, s1);
        s0 = fmaf(w10, fa2.x, s0);  s1 = fmaf(w10, fa2.y, s1);
        s0 = fmaf(w11, fa3.x, s0);  s1 = fmaf(w11, fa3.y, s1);
        // ox = 1 (weight factor tx)
        float q0 = 0.0f, q1 = 0.0f;
        q0 = fmaf(w00, fb0.x, q0);  q1 = fmaf(w00, fb0.y, q1);
        q0 = fmaf(w01, fb1.x, q0);  q1 = fmaf(w01, fb1.y, q1);
        q0 = fmaf(w10, fb2.x, q0);  q1 = fmaf(w10, fb2.y, q1);
        q0 = fmaf(w11, fb3.x, q0);  q1 = fmaf(w11, fb3.y, q1);
        e0 = fmaf(ux, s0, tx * q0);
        e1 = fmaf(ux, s1, tx * q1);

        *reinterpret_cast<float2*>(&semb[tid][2 * l]) = make_float2(e0, e1);
        acc256 = fmaf(e0, wc256[2 * l + 0], acc256);
        acc256 = fmaf(e1, wc256[2 * l + 1], acc256);
    }

    // odd 257th column, streaming store
    __stcs(out + (size_t)p * D_OUT + 256, acc256);

    __syncthreads();

    // ------- Phase 2: GEMM head. Thread owns 4 strided columns {t, t+64, t+128, t+192}.
    unsigned long long wreg[L_LEVELS][4];   // 12 k-pairs x 4 columns (96 regs)
#pragma unroll
    for (int kk = 0; kk < L_LEVELS; kk++) {
#pragma unroll
        for (int c = 0; c < 4; c++) {
            int col = tid + 64 * c;
            wreg[kk][c] = pack2(W[(2 * kk) * D_OUT + col], W[(2 * kk + 1) * D_OUT + col]);
        }
    }
    float breg[4];
#pragma unroll
    for (int c = 0; c < 4; c++) breg[c] = bias[tid + 64 * c];

    float* outb = out + (size_t)blockIdx.x * BLOCK * D_OUT;

#pragma unroll 2
    for (int r = 0; r < BLOCK; r++) {
        const float4* erow = reinterpret_cast<const float4*>(&semb[r][0]);
        unsigned long long a0 = 0, a1 = 0, a2 = 0, a3 = 0;
#pragma unroll
        for (int q = 0; q < 6; q++) {
            float4 e4 = erow[q];                 // broadcast LDS.128: 4 features
            unsigned long long p0 = pack2(e4.x, e4.y);   // (e_{4q},   e_{4q+1})
            unsigned long long p1 = pack2(e4.z, e4.w);   // (e_{4q+2}, e_{4q+3})
            a0 = fma2(p0, wreg[2 * q][0], a0);  a0 = fma2(p1, wreg[2 * q + 1][0], a0);
            a1 = fma2(p0, wreg[2 * q][1], a1);  a1 = fma2(p1, wreg[2 * q + 1][1], a1);
            a2 = fma2(p0, wreg[2 * q][2], a2);  a2 = fma2(p1, wreg[2 * q + 1][2], a2);
            a3 = fma2(p0, wreg[2 * q][3], a3);  a3 = fma2(p1, wreg[2 * q + 1][3], a3);
        }
        float lo, hi;
        float* orow = outb + (size_t)r * D_OUT;
        unpack2(a0, lo, hi); __stcs(orow + tid,       lo + hi + breg[0]);
        unpack2(a1, lo, hi); __stcs(orow + tid +  64, lo + hi + breg[1]);
        unpack2(a2, lo, hi); __stcs(orow + tid + 128, lo + hi + breg[2]);
        unpack2(a3, lo, hi); __stcs(orow + tid + 192, lo + hi + breg[3]);
    }
}

extern "C" void kernel_launch(void* const* d_in, const int* in_sizes, int n_in,
                              void* d_out, int out_size) {
    const float*  xin  = (const float*) d_in[0];   // [N,3]
    const float2* tab  = (const float2*)d_in[1];   // [12,T,2] -> float2
    const float*  W    = (const float*) d_in[2];   // [24,257]
    const float*  bias = (const float*) d_in[3];   // [257]
    float* out = (float*)d_out;

    dim3 grid(N_POINTS / BLOCK);   // 8192 blocks, 64 points each
    hashgrid_fused_kernel<<<grid, BLOCK>>>(xin, tab, W, bias, out);
}

// round 7
// speedup vs baseline: 1.0480x; 1.0480x over previous
#include <cuda_runtime.h>
#include <cstdint>

#define L_LEVELS 12
#define T_SIZE   (1u << 19)
#define T_MASK   (T_SIZE - 1u)
#define N_POINTS 524288
#define D_OUT    257
#define FEAT     24          // L * F
#define BLOCK    128         // 4 warps: 0-1 producers (encode), 2-3 consumers (GEMM)
#define TPW      64          // points per tile
#define TILES    8           // tiles per block
#define EMB_PAD  28          // padded row stride in floats (16B aligned, 7 float4s)

// ---------- packed f32x2 helpers (Blackwell FFMA2 path) ----------
__device__ __forceinline__ unsigned long long pack2(float lo, float hi) {
    unsigned long long r;
    asm("mov.b64 %0, {%1, %2};" : "=l"(r) : "f"(lo), "f"(hi));
    return r;
}
__device__ __forceinline__ void unpack2(unsigned long long v, float& lo, float& hi) {
    asm("mov.b64 {%0, %1}, %2;" : "=f"(lo), "=f"(hi) : "l"(v));
}
__device__ __forceinline__ unsigned long long fma2(unsigned long long a,
                                                   unsigned long long b,
                                                   unsigned long long c) {
    unsigned long long d;
    asm("fma.rn.f32x2 %0, %1, %2, %3;" : "=l"(d) : "l"(a), "l"(b), "l"(c));
    return d;
}

// Per-level grid resolutions: floor(16 * growth^l), growth = exp(ln(128)/11).
__device__ __constant__ float RESF[L_LEVELS] = {
    16.f, 24.f, 38.f, 60.f, 93.f, 145.f, 225.f, 350.f, 545.f, 847.f, 1317.f, 2048.f
};

__global__ __launch_bounds__(BLOCK, 4)
void hashgrid_fused_kernel(const float*  __restrict__ xin,    // [N,3]
                           const float2* __restrict__ tab,    // [12, T] of float2
                           const float*  __restrict__ W,      // [24, 257]
                           const float*  __restrict__ bias,   // [257]
                           float*        __restrict__ out)    // [N, 257]
{
    __shared__ float semb[2][TPW][EMB_PAD];  // double-buffered embeddings
    __shared__ float wc256[FEAT];            // W[:,256]
    __shared__ float b256s;

    const int tid = threadIdx.x;
    const bool producer = tid < TPW;         // warps 0-1
    const int  ctid = tid - TPW;             // consumer lane id 0..63

    if (tid < FEAT) wc256[tid] = W[tid * D_OUT + 256];
    if (tid == FEAT) b256s = bias[256];

    const unsigned P1 = 2654435761u;
    const unsigned P2 = 805459861u;
    const int baseP = blockIdx.x * (TPW * TILES);   // first point of this block

    // ---- consumer setup: per-thread weights for 4 strided columns ----
    unsigned long long wreg[L_LEVELS][4];   // 96 regs (consumers only use them)
    float breg[4];
    if (!producer) {
#pragma unroll
        for (int kk = 0; kk < L_LEVELS; kk++) {
#pragma unroll
            for (int c = 0; c < 4; c++) {
                int col = ctid + 64 * c;
                wreg[kk][c] = pack2(W[(2 * kk) * D_OUT + col], W[(2 * kk + 1) * D_OUT + col]);
            }
        }
#pragma unroll
        for (int c = 0; c < 4; c++) breg[c] = bias[ctid + 64 * c];
    }
    __syncthreads();   // wc256/b256s visible to producers

    // ---- prologue: producers encode tile 0 into buffer 0 ----
    if (producer) {
        const int p = baseP + tid;
        const float x = xin[3 * p + 0];
        const float y = xin[3 * p + 1];
        const float z = xin[3 * p + 2];
        float acc256 = b256s;
#pragma unroll
        for (int l = 0; l < L_LEVELS; l++) {
            const float resf = RESF[l];
            const float2* tl = tab + (size_t)l * T_SIZE;
            float px = x * resf, py = y * resf, pz = z * resf;
            float fx = floorf(px), fy = floorf(py), fz = floorf(pz);
            float tx = px - fx,   ty = py - fy,   tz = pz - fz;
            unsigned cx = (unsigned)fx, cy = (unsigned)fy, cz = (unsigned)fz;
            unsigned hx0 = cx,        hx1 = cx + 1u;
            unsigned hy0 = cy * P1,   hy1 = hy0 + P1;
            unsigned hz0 = cz * P2,   hz1 = hz0 + P2;
            float2 f[8];
            f[0] = __ldg(tl + ((hx0 ^ hy0 ^ hz0) & T_MASK));
            f[1] = __ldg(tl + ((hx0 ^ hy0 ^ hz1) & T_MASK));
            f[2] = __ldg(tl + ((hx0 ^ hy1 ^ hz0) & T_MASK));
            f[3] = __ldg(tl + ((hx0 ^ hy1 ^ hz1) & T_MASK));
            f[4] = __ldg(tl + ((hx1 ^ hy0 ^ hz0) & T_MASK));
            f[5] = __ldg(tl + ((hx1 ^ hy0 ^ hz1) & T_MASK));
            f[6] = __ldg(tl + ((hx1 ^ hy1 ^ hz0) & T_MASK));
            f[7] = __ldg(tl + ((hx1 ^ hy1 ^ hz1) & T_MASK));
            const float ux = 1.0f - tx, uy = 1.0f - ty, uz = 1.0f - tz;
            float wxy[4];
            wxy[0] = ux * uy; wxy[1] = ux * ty; wxy[2] = tx * uy; wxy[3] = tx * ty;
            float e0 = 0.0f, e1 = 0.0f;
#pragma unroll
            for (int i = 0; i < 8; i++) {
                float w = wxy[i >> 1] * ((i & 1) ? tz : uz);
                e0 = fmaf(w, f[i].x, e0);
                e1 = fmaf(w, f[i].y, e1);
            }
            *reinterpret_cast<float2*>(&semb[0][tid][2 * l]) = make_float2(e0, e1);
            acc256 = fmaf(e0, wc256[2 * l + 0], acc256);
            acc256 = fmaf(e1, wc256[2 * l + 1], acc256);
        }
        __stcs(out + (size_t)p * D_OUT + 256, acc256);
    }
    __syncthreads();

    // ---- pipelined main loop ----
    for (int t = 0; t < TILES; t++) {
        // producers: encode tile t+1 into buffer (t+1)&1
        if (producer && (t + 1 < TILES)) {
            const int p = baseP + (t + 1) * TPW + tid;
            float* srow = &semb[(t + 1) & 1][tid][0];
            const float x = xin[3 * p + 0];
            const float y = xin[3 * p + 1];
            const float z = xin[3 * p + 2];
            float acc256 = b256s;
#pragma unroll
            for (int l = 0; l < L_LEVELS; l++) {
                const float resf = RESF[l];
                const float2* tl = tab + (size_t)l * T_SIZE;
                float px = x * resf, py = y * resf, pz = z * resf;
                float fx = floorf(px), fy = floorf(py), fz = floorf(pz);
                float tx = px - fx,   ty = py - fy,   tz = pz - fz;
                unsigned cx = (unsigned)fx, cy = (unsigned)fy, cz = (unsigned)fz;
                unsigned hx0 = cx,        hx1 = cx + 1u;
                unsigned hy0 = cy * P1,   hy1 = hy0 + P1;
                unsigned hz0 = cz * P2,   hz1 = hz0 + P2;
                float2 f[8];
                f[0] = __ldg(tl + ((hx0 ^ hy0 ^ hz0) & T_MASK));
                f[1] = __ldg(tl + ((hx0 ^ hy0 ^ hz1) & T_MASK));
                f[2] = __ldg(tl + ((hx0 ^ hy1 ^ hz0) & T_MASK));
                f[3] = __ldg(tl + ((hx0 ^ hy1 ^ hz1) & T_MASK));
                f[4] = __ldg(tl + ((hx1 ^ hy0 ^ hz0) & T_MASK));
                f[5] = __ldg(tl + ((hx1 ^ hy0 ^ hz1) & T_MASK));
                f[6] = __ldg(tl + ((hx1 ^ hy1 ^ hz0) & T_MASK));
                f[7] = __ldg(tl + ((hx1 ^ hy1 ^ hz1) & T_MASK));
                const float ux = 1.0f - tx, uy = 1.0f - ty, uz = 1.0f - tz;
                float wxy[4];
                wxy[0] = ux * uy; wxy[1] = ux * ty; wxy[2] = tx * uy; wxy[3] = tx * ty;
                float e0 = 0.0f, e1 = 0.0f;
#pragma unroll
                for (int i = 0; i < 8; i++) {
                    float w = wxy[i >> 1] * ((i & 1) ? tz : uz);
                    e0 = fmaf(w, f[i].x, e0);
                    e1 = fmaf(w, f[i].y, e1);
                }
                *reinterpret_cast<float2*>(&srow[2 * l]) = make_float2(e0, e1);
                acc256 = fmaf(e0, wc256[2 * l + 0], acc256);
                acc256 = fmaf(e1, wc256[2 * l + 1], acc256);
            }
            __stcs(out + (size_t)p * D_OUT + 256, acc256);
        }

        // consumers: GEMM tile t from buffer t&1
        if (!producer) {
            const float (*buf)[EMB_PAD] = semb[t & 1];
            float* outb = out + (size_t)(baseP + t * TPW) * D_OUT;
#pragma unroll 2
            for (int r = 0; r < TPW; r++) {
                const float4* erow = reinterpret_cast<const float4*>(&buf[r][0]);
                unsigned long long a0 = 0, a1 = 0, a2 = 0, a3 = 0;
#pragma unroll
                for (int q = 0; q < 6; q++) {
                    float4 e4 = erow[q];                 // broadcast LDS.128
                    unsigned long long p0 = pack2(e4.x, e4.y);
                    unsigned long long p1 = pack2(e4.z, e4.w);
                    a0 = fma2(p0, wreg[2 * q][0], a0);  a0 = fma2(p1, wreg[2 * q + 1][0], a0);
                    a1 = fma2(p0, wreg[2 * q][1], a1);  a1 = fma2(p1, wreg[2 * q + 1][1], a1);
                    a2 = fma2(p0, wreg[2 * q][2], a2);  a2 = fma2(p1, wreg[2 * q + 1][2], a2);
                    a3 = fma2(p0, wreg[2 * q][3], a3);  a3 = fma2(p1, wreg[2 * q + 1][3], a3);
                }
                float lo, hi;
                float* orow = outb + (size_t)r * D_OUT;
                unpack2(a0, lo, hi); __stcs(orow + ctid,       lo + hi + breg[0]);
                unpack2(a1, lo, hi); __stcs(orow + ctid +  64, lo + hi + breg[1]);
                unpack2(a2, lo, hi); __stcs(orow + ctid + 128, lo + hi + breg[2]);
                unpack2(a3, lo, hi); __stcs(orow + ctid + 192, lo + hi + breg[3]);
            }
        }

        __syncthreads();   // producers' buffer (t+1)&1 full; consumers done with t&1
    }
}

extern "C" void kernel_launch(void* const* d_in, const int* in_sizes, int n_in,
                              void* d_out, int out_size) {
    const float*  xin  = (const float*) d_in[0];   // [N,3]
    const float2* tab  = (const float2*)d_in[1];   // [12,T,2] -> float2
    const float*  W    = (const float*) d_in[2];   // [24,257]
    const float*  bias = (const float*) d_in[3];   // [257]
    float* out = (float*)d_out;

    dim3 grid(N_POINTS / (TPW * TILES));   // 1024 blocks, 512 points each
    hashgrid_fused_kernel<<<grid, BLOCK>>>(xin, tab, W, bias, out);
}

// round 8
// speedup vs baseline: 1.1265x; 1.0749x over previous
#include <cuda_runtime.h>
#include <cstdint>

#define L_LEVELS 12
#define T_SIZE   (1u << 19)
#define T_MASK   (T_SIZE - 1u)
#define N_POINTS 524288
#define D_OUT    257
#define FEAT     24          // L * F
#define BLOCK    64          // threads per block = points per block (2 warps)
#define EMB_PAD  28          // padded row stride in floats (16B aligned, 7 float4s)

// ---------- packed f32x2 helpers (Blackwell FFMA2 path) ----------
__device__ __forceinline__ unsigned long long pack2(float lo, float hi) {
    unsigned long long r;
    asm("mov.b64 %0, {%1, %2};" : "=l"(r) : "f"(lo), "f"(hi));
    return r;
}
__device__ __forceinline__ void unpack2(unsigned long long v, float& lo, float& hi) {
    asm("mov.b64 {%0, %1}, %2;" : "=f"(lo), "=f"(hi) : "l"(v));
}
__device__ __forceinline__ unsigned long long fma2(unsigned long long a,
                                                   unsigned long long b,
                                                   unsigned long long c) {
    unsigned long long d;
    asm("fma.rn.f32x2 %0, %1, %2, %3;" : "=l"(d) : "l"(a), "l"(b), "l"(c));
    return d;
}

// Per-level grid resolutions: floor(16 * growth^l), growth = exp(ln(128)/11).
__device__ __constant__ float RESF[L_LEVELS] = {
    16.f, 24.f, 38.f, 60.f, 93.f, 145.f, 225.f, 350.f, 545.f, 847.f, 1317.f, 2048.f
};

// Gather the (ox=0, ox=1) corner pair for one (oy,oz) r-hash.
// When cx is even, idx1 == idx0^1: both entries live in one aligned 16B pair
// -> single LDG.128 (1 L1 wavefront instead of 2). Otherwise two LDG.64.
// merged: 1 if cx even. Output t[0..3]; logical order resolved by weight swap.
__device__ __forceinline__ void gather_pair(const float2* __restrict__ tl,
                                            unsigned cx, unsigned r, unsigned merged,
                                            float& t0, float& t1, float& t2, float& t3)
{
    unsigned i0 = (cx        ^ r) & T_MASK;
    unsigned i1 = ((cx + 1u) ^ r) & T_MASK;
    const char* base = (const char*)tl;
    const float* p128 = (const float*)(base + ((size_t)(i0 & ~1u) << 3));
    const float* pa   = (const float*)(base + ((size_t)i0 << 3));
    const float* pb   = (const float*)(base + ((size_t)i1 << 3));
    asm("{\n\t"
        ".reg .pred p;\n\t"
        "setp.ne.u32 p, %4, 0;\n\t"
        "@p  ld.global.nc.v4.f32 {%0,%1,%2,%3}, [%5];\n\t"
        "@!p ld.global.nc.v2.f32 {%0,%1}, [%6];\n\t"
        "@!p ld.global.nc.v2.f32 {%2,%3}, [%7];\n\t"
        "}"
        : "=f"(t0), "=f"(t1), "=f"(t2), "=f"(t3)
        : "r"(merged), "l"(p128), "l"(pa), "l"(pb));
}

__global__ __launch_bounds__(BLOCK, 7)   // 146 regs available: NO spills (R6 bug)
void hashgrid_fused_kernel(const float*  __restrict__ xin,    // [N,3]
                           const float2* __restrict__ tab,    // [12, T] of float2
                           const float*  __restrict__ W,      // [24, 257]
                           const float*  __restrict__ bias,   // [257]
                           float*        __restrict__ out)    // [N, 257]
{
    __shared__ float semb[BLOCK][EMB_PAD];  // 24 features/row, padded to 28
    __shared__ float wc256[FEAT];           // W[:,256]
    __shared__ float b256s;

    const int tid = threadIdx.x;

    if (tid < FEAT) wc256[tid] = W[tid * D_OUT + 256];
    if (tid == FEAT) b256s = bias[256];
    __syncthreads();

    // ---------------- Phase 1: hash encode (thread = point) ----------------
    const int p = blockIdx.x * BLOCK + tid;
    const float x = xin[3 * p + 0];
    const float y = xin[3 * p + 1];
    const float z = xin[3 * p + 2];

    const unsigned P1 = 2654435761u;
    const unsigned P2 = 805459861u;

    float acc256 = b256s;

#pragma unroll
    for (int l = 0; l < L_LEVELS; l++) {
        const float resf = RESF[l];
        const float2* tl = tab + (size_t)l * T_SIZE;

        float px = x * resf, py = y * resf, pz = z * resf;
        float fx = floorf(px), fy = floorf(py), fz = floorf(pz);
        float tx = px - fx,   ty = py - fy,   tz = pz - fz;

        unsigned cx = (unsigned)fx, cy = (unsigned)fy, cz = (unsigned)fz;
        unsigned merged = (cx & 1u) ^ 1u;        // 1 if cx even (pair contiguous)
        unsigned hy0 = cy * P1,   hy1 = hy0 + P1;
        unsigned hz0 = cz * P2,   hz1 = hz0 + P2;
        unsigned r0 = hy0 ^ hz0, r1 = hy0 ^ hz1, r2 = hy1 ^ hz0, r3 = hy1 ^ hz1;

        // 4 (oy,oz) pairs, each = (ox=0, ox=1) corner pair in t[4*j..4*j+3]
        float t00,t01,t02,t03, t10,t11,t12,t13, t20,t21,t22,t23, t30,t31,t32,t33;
        gather_pair(tl, cx, r0, merged, t00,t01,t02,t03);
        gather_pair(tl, cx, r1, merged, t10,t11,t12,t13);
        gather_pair(tl, cx, r2, merged, t20,t21,t22,t23);
        gather_pair(tl, cx, r3, merged, t30,t31,t32,t33);

        const float ux = 1.0f - tx, uy = 1.0f - ty, uz = 1.0f - tz;
        float wyz0 = uy * uz, wyz1 = uy * tz, wyz2 = ty * uz, wyz3 = ty * tz;

        // If merged and i0 odd (i.e. r odd, since cx even), the 16B pair holds
        // (f(i1), f(i0)) -> swap which weight hits which half.
        float e0 = 0.0f, e1 = 0.0f;
        {
            unsigned sw = merged & r0 & 1u;
            float uw = ux * wyz0, tw = tx * wyz0;
            float wlo = sw ? tw : uw, whi = sw ? uw : tw;
            e0 = fmaf(wlo, t00, e0); e1 = fmaf(wlo, t01, e1);
            e0 = fmaf(whi, t02, e0); e1 = fmaf(whi, t03, e1);
        }
        {
            unsigned sw = merged & r1 & 1u;
            float uw = ux * wyz1, tw = tx * wyz1;
            float wlo = sw ? tw : uw, whi = sw ? uw : tw;
            e0 = fmaf(wlo, t10, e0); e1 = fmaf(wlo, t11, e1);
            e0 = fmaf(whi, t12, e0); e1 = fmaf(whi, t13, e1);
        }
        {
            unsigned sw = merged & r2 & 1u;
            float uw = ux * wyz2, tw = tx * wyz2;
            float wlo = sw ? tw : uw, whi = sw ? uw : tw;
            e0 = fmaf(wlo, t20, e0); e1 = fmaf(wlo, t21, e1);
            e0 = fmaf(whi, t22, e0); e1 = fmaf(whi, t23, e1);
        }
        {
            unsigned sw = merged & r3 & 1u;
            float uw = ux * wyz3, tw = tx * wyz3;
            float wlo = sw ? tw : uw, whi = sw ? uw : tw;
            e0 = fmaf(wlo, t30, e0); e1 = fmaf(wlo, t31, e1);
            e0 = fmaf(whi, t32, e0); e1 = fmaf(whi, t33, e1);
        }

        *reinterpret_cast<float2*>(&semb[tid][2 * l]) = make_float2(e0, e1);
        acc256 = fmaf(e0, wc256[2 * l + 0], acc256);
        acc256 = fmaf(e1, wc256[2 * l + 1], acc256);
    }

    // odd 257th column, streaming store
    __stcs(out + (size_t)p * D_OUT + 256, acc256);

    __syncthreads();

    // ------- Phase 2: GEMM head. Thread owns 4 strided columns {t, t+64, t+128, t+192}.
    unsigned long long wreg[L_LEVELS][4];   // 12 k-pairs x 4 columns (96 regs)
#pragma unroll
    for (int kk = 0; kk < L_LEVELS; kk++) {
#pragma unroll
        for (int c = 0; c < 4; c++) {
            int col = tid + 64 * c;
            wreg[kk][c] = pack2(W[(2 * kk) * D_OUT + col], W[(2 * kk + 1) * D_OUT + col]);
        }
    }
    float breg[4];
#pragma unroll
    for (int c = 0; c < 4; c++) breg[c] = bias[tid + 64 * c];

    float* outb = out + (size_t)blockIdx.x * BLOCK * D_OUT;

#pragma unroll 2
    for (int r = 0; r < BLOCK; r++) {
        const float4* erow = reinterpret_cast<const float4*>(&semb[r][0]);
        unsigned long long a0 = 0, a1 = 0, a2 = 0, a3 = 0;
#pragma unroll
        for (int q = 0; q < 6; q++) {
            float4 e4 = erow[q];                 // broadcast LDS.128: 4 features
            unsigned long long p0 = pack2(e4.x, e4.y);   // (e_{4q},   e_{4q+1})
            unsigned long long p1 = pack2(e4.z, e4.w);   // (e_{4q+2}, e_{4q+3})
            a0 = fma2(p0, wreg[2 * q][0], a0);  a0 = fma2(p1, wreg[2 * q + 1][0], a0);
            a1 = fma2(p0, wreg[2 * q][1], a1);  a1 = fma2(p1, wreg[2 * q + 1][1], a1);
            a2 = fma2(p0, wreg[2 * q][2], a2);  a2 = fma2(p1, wreg[2 * q + 1][2], a2);
            a3 = fma2(p0, wreg[2 * q][3], a3);  a3 = fma2(p1, wreg[2 * q + 1][3], a3);
        }
        float lo, hi;
        float* orow = outb + (size_t)r * D_OUT;
        unpack2(a0, lo, hi); __stcs(orow + tid,       lo + hi + breg[0]);
        unpack2(a1, lo, hi); __stcs(orow + tid +  64, lo + hi + breg[1]);
        unpack2(a2, lo, hi); __stcs(orow + tid + 128, lo + hi + breg[2]);
        unpack2(a3, lo, hi); __stcs(orow + tid + 192, lo + hi + breg[3]);
    }
}

extern "C" void kernel_launch(void* const* d_in, const int* in_sizes, int n_in,
                              void* d_out, int out_size) {
    const float*  xin  = (const float*) d_in[0];   // [N,3]
    const float2* tab  = (const float2*)d_in[1];   // [12,T,2] -> float2
    const float*  W    = (const float*) d_in[2];   // [24,257]
    const float*  bias = (const float*) d_in[3];   // [257]
    float* out = (float*)d_out;

    dim3 grid(N_POINTS / BLOCK);   // 8192 blocks, 64 points each
    hashgrid_fused_kernel<<<grid, BLOCK>>>(xin, tab, W, bias, out);
}

// round 9
// speedup vs baseline: 1.4156x; 1.2566x over previous
#include <cuda_runtime.h>
#include <cstdint>

#define L_LEVELS 12
#define T_SIZE   (1u << 19)
#define T_MASK   (T_SIZE - 1u)
#define N_POINTS 524288
#define D_OUT    257
#define FEAT     24          // L * F
#define BLOCK    32          // one warp per block: fully autonomous tile
#define EMB_PAD  28          // padded row stride in floats (16B aligned, 7 float4s)

// ---------- packed f32x2 helpers (Blackwell FFMA2 path) ----------
__device__ __forceinline__ unsigned long long pack2(float lo, float hi) {
    unsigned long long r;
    asm("mov.b64 %0, {%1, %2};" : "=l"(r) : "f"(lo), "f"(hi));
    return r;
}
__device__ __forceinline__ void unpack2(unsigned long long v, float& lo, float& hi) {
    asm("mov.b64 {%0, %1}, %2;" : "=f"(lo), "=f"(hi) : "l"(v));
}
__device__ __forceinline__ unsigned long long fma2(unsigned long long a,
                                                   unsigned long long b,
                                                   unsigned long long c) {
    unsigned long long d;
    asm("fma.rn.f32x2 %0, %1, %2, %3;" : "=l"(d) : "l"(a), "l"(b), "l"(c));
    return d;
}

// Per-level grid resolutions: floor(16 * growth^l), growth = exp(ln(128)/11).
__device__ __constant__ float RESF[L_LEVELS] = {
    16.f, 24.f, 38.f, 60.f, 93.f, 145.f, 225.f, 350.f, 545.f, 847.f, 1317.f, 2048.f
};

__global__ __launch_bounds__(BLOCK, 16)
void hashgrid_fused_kernel(const float*  __restrict__ xin,    // [N,3]
                           const float2* __restrict__ tab,    // [12, T] of float2
                           const float*  __restrict__ W,      // [24, 257]
                           const float*  __restrict__ bias,   // [257]
                           float*        __restrict__ out)    // [N, 257]
{
    __shared__ float semb[BLOCK][EMB_PAD];  // 24 features/row (this warp's tile)
    __shared__ float wc256[FEAT];           // W[:,256]
    __shared__ float b256s;

    const int tid = threadIdx.x;            // lane id, 0..31

    if (tid < FEAT) wc256[tid] = W[tid * D_OUT + 256];
    if (tid == FEAT) b256s = bias[256];
    __syncwarp();

    // ---------------- Phase 1: hash encode (lane = point) ----------------
    const int p = blockIdx.x * BLOCK + tid;
    const float x = xin[3 * p + 0];
    const float y = xin[3 * p + 1];
    const float z = xin[3 * p + 2];

    const unsigned P1 = 2654435761u;
    const unsigned P2 = 805459861u;

    float acc256 = b256s;

#pragma unroll
    for (int l = 0; l < L_LEVELS; l++) {
        const float resf = RESF[l];
        const float2* tl = tab + (size_t)l * T_SIZE;

        float px = x * resf, py = y * resf, pz = z * resf;
        float fx = floorf(px), fy = floorf(py), fz = floorf(pz);
        float tx = px - fx,   ty = py - fy,   tz = pz - fz;

        unsigned cx = (unsigned)fx, cy = (unsigned)fy, cz = (unsigned)fz;
        unsigned hx0 = cx,        hx1 = cx + 1u;
        unsigned hy0 = cy * P1,   hy1 = hy0 + P1;
        unsigned hz0 = cz * P2,   hz1 = hz0 + P2;

        float2 f[8];
        f[0] = __ldg(tl + ((hx0 ^ hy0 ^ hz0) & T_MASK));
        f[1] = __ldg(tl + ((hx0 ^ hy0 ^ hz1) & T_MASK));
        f[2] = __ldg(tl + ((hx0 ^ hy1 ^ hz0) & T_MASK));
        f[3] = __ldg(tl + ((hx0 ^ hy1 ^ hz1) & T_MASK));
        f[4] = __ldg(tl + ((hx1 ^ hy0 ^ hz0) & T_MASK));
        f[5] = __ldg(tl + ((hx1 ^ hy0 ^ hz1) & T_MASK));
        f[6] = __ldg(tl + ((hx1 ^ hy1 ^ hz0) & T_MASK));
        f[7] = __ldg(tl + ((hx1 ^ hy1 ^ hz1) & T_MASK));

        const float ux = 1.0f - tx, uy = 1.0f - ty, uz = 1.0f - tz;
        float wxy[4];
        wxy[0] = ux * uy;
        wxy[1] = ux * ty;
        wxy[2] = tx * uy;
        wxy[3] = tx * ty;

        float e0 = 0.0f, e1 = 0.0f;
#pragma unroll
        for (int i = 0; i < 8; i++) {
            float w = wxy[i >> 1] * ((i & 1) ? tz : uz);
            e0 = fmaf(w, f[i].x, e0);
            e1 = fmaf(w, f[i].y, e1);
        }

        *reinterpret_cast<float2*>(&semb[tid][2 * l]) = make_float2(e0, e1);
        acc256 = fmaf(e0, wc256[2 * l + 0], acc256);
        acc256 = fmaf(e1, wc256[2 * l + 1], acc256);
    }

    // odd 257th column, streaming store
    __stcs(out + (size_t)p * D_OUT + 256, acc256);

    __syncwarp();   // warp-local: this warp wrote all 32 rows itself

    // ------- Phase 2: GEMM head, 2 passes of 128 columns (4 per lane).
    // Pass p covers cols 128p + lane + {0,32,64,96}. W regs reloaded per pass
    // (coalesced, L1-resident). Packed over k; horizontal add at the end.
    float* outb = out + (size_t)blockIdx.x * BLOCK * D_OUT;

#pragma unroll
    for (int pass = 0; pass < 2; pass++) {
        const int cbase = 128 * pass + tid;

        unsigned long long wreg[L_LEVELS][4];   // 48 packed = 96 regs
#pragma unroll
        for (int kk = 0; kk < L_LEVELS; kk++) {
#pragma unroll
            for (int c = 0; c < 4; c++) {
                int col = cbase + 32 * c;
                wreg[kk][c] = pack2(W[(2 * kk) * D_OUT + col],
                                    W[(2 * kk + 1) * D_OUT + col]);
            }
        }
        float breg[4];
#pragma unroll
        for (int c = 0; c < 4; c++) breg[c] = bias[cbase + 32 * c];

#pragma unroll 2
        for (int r = 0; r < BLOCK; r++) {
            const float4* erow = reinterpret_cast<const float4*>(&semb[r][0]);
            unsigned long long a0 = 0, a1 = 0, a2 = 0, a3 = 0;
#pragma unroll
            for (int q = 0; q < 6; q++) {
                float4 e4 = erow[q];                 // broadcast LDS.128: 4 features
                unsigned long long p0 = pack2(e4.x, e4.y);
                unsigned long long p1 = pack2(e4.z, e4.w);
                a0 = fma2(p0, wreg[2 * q][0], a0);  a0 = fma2(p1, wreg[2 * q + 1][0], a0);
                a1 = fma2(p0, wreg[2 * q][1], a1);  a1 = fma2(p1, wreg[2 * q + 1][1], a1);
                a2 = fma2(p0, wreg[2 * q][2], a2);  a2 = fma2(p1, wreg[2 * q + 1][2], a2);
                a3 = fma2(p0, wreg[2 * q][3], a3);  a3 = fma2(p1, wreg[2 * q + 1][3], a3);
            }
            float lo, hi;
            float* orow = outb + (size_t)r * D_OUT + cbase;
            unpack2(a0, lo, hi); __stcs(orow +  0, lo + hi + breg[0]);
            unpack2(a1, lo, hi); __stcs(orow + 32, lo + hi + breg[1]);
            unpack2(a2, lo, hi); __stcs(orow + 64, lo + hi + breg[2]);
            unpack2(a3, lo, hi); __stcs(orow + 96, lo + hi + breg[3]);
        }
    }
}

extern "C" void kernel_launch(void* const* d_in, const int* in_sizes, int n_in,
                              void* d_out, int out_size) {
    const float*  xin  = (const float*) d_in[0];   // [N,3]
    const float2* tab  = (const float2*)d_in[1];   // [12,T,2] -> float2
    const float*  W    = (const float*) d_in[2];   // [24,257]
    const float*  bias = (const float*) d_in[3];   // [257]
    float* out = (float*)d_out;

    dim3 grid(N_POINTS / BLOCK);   // 16384 blocks, 32 points each
    hashgrid_fused_kernel<<<grid, BLOCK>>>(xin, tab, W, bias, out);
}